// round 16
// baseline (speedup 1.0000x reference)
#include <cuda_runtime.h>
#include <cuda_bf16.h>
#include <math.h>
#include <cstdint>

#define N_NODES 8192
#define FOUT 64
#define TILE_M 64
#define JTILES 32            // per CTA: 32 tiles x 64 cols (j-split = 4)
#define LRELU_ALPHA 0.2f
#define LOG2E 1.4426950408889634f

#define S2_SZ 8192
#define P_SZ 9216            // 64 rows x 144 B
#define OFF_P S2_SZ
#define SMEM_BYTES (S2_SZ + 2 * P_SZ)   // 26624 -> 4 CTAs/SM
#define PART_STRIDE 66
#define B_TILE_BYTES 8192    // 4 ksteps x 2048 B (N=64, no ones col)

// ---------------- device scratch (no allocation allowed) -------------------
__device__ __align__(256) uint32_t g_Bpack[512 * 512 + 256];
__device__ __align__(256) uint32_t g_mask[N_NODES * 256];
__device__ __align__(256) float g_part[512 * TILE_M * PART_STRIDE];
__device__ float g_s1[N_NODES];          // pre-scaled by LOG2E
__device__ float g_s2[N_NODES];          // pre-scaled by LOG2E

// ---------------- helpers ----------------------------------------------------
__device__ __forceinline__ uint32_t smem_u32(const void* p) {
    uint32_t a;
    asm("{ .reg .u64 t; cvta.to.shared.u64 t, %1; cvt.u32.u64 %0, t; }" : "=r"(a) : "l"(p));
    return a;
}
__device__ __forceinline__ float ex2(float x) {
    float r;
    asm("ex2.approx.f32 %0, %1;" : "=f"(r) : "f"(x));
    return r;
}
__device__ __forceinline__ uint32_t lds32(uint32_t a) {
    uint32_t v; asm("ld.shared.b32 %0, [%1];" : "=r"(v) : "r"(a)); return v;
}
__device__ __forceinline__ void sts64(uint32_t a, uint32_t v0, uint32_t v1) {
    asm volatile("st.shared.v2.b32 [%0], {%1,%2};" :: "r"(a), "r"(v0), "r"(v1) : "memory");
}
__device__ __forceinline__ void sts128(uint32_t a, uint32_t v0, uint32_t v1, uint32_t v2, uint32_t v3) {
    asm volatile("st.shared.v4.b32 [%0], {%1,%2,%3,%4};" :: "r"(a), "r"(v0), "r"(v1), "r"(v2), "r"(v3) : "memory");
}
__device__ __forceinline__ void mma_bf16(float* c,
                                         uint32_t a0, uint32_t a1, uint32_t a2, uint32_t a3,
                                         uint32_t b0, uint32_t b1) {
    asm("mma.sync.aligned.m16n8k16.row.col.f32.bf16.bf16.f32 "
        "{%0,%1,%2,%3},{%4,%5,%6,%7},{%8,%9},{%0,%1,%2,%3};"
        : "+f"(c[0]), "+f"(c[1]), "+f"(c[2]), "+f"(c[3])
        : "r"(a0), "r"(a1), "r"(a2), "r"(a3), "r"(b0), "r"(b1));
}

// ---------------------------------------------------------------------------
// Kernel 0: pack adj>0 into row-major bitmask g_mask[row][word] via ballot.
// ---------------------------------------------------------------------------
__global__ __launch_bounds__(256) void pack_kernel(const int* __restrict__ adj) {
    __shared__ uint32_t sm[32][9];
    const int tid  = threadIdx.x;
    const int lane = tid & 31;
    const int widx = tid >> 5;
    const int rb = blockIdx.x >> 5;
    const int wb = blockIdx.x & 31;
#pragma unroll
    for (int rr = 0; rr < 4; rr++) {
        const int row = rb * 32 + widx * 4 + rr;
        const int* __restrict__ arow = adj + (size_t)row * N_NODES + wb * 256;
#pragma unroll
        for (int w = 0; w < 8; w++) {
            const int v = __ldcs(arow + w * 32 + lane);
            const uint32_t b = __ballot_sync(0xFFFFFFFFu, v > 0);
            if (lane == w) sm[widx * 4 + rr][w] = b;
        }
    }
    __syncthreads();
    const int row = tid >> 3, w = tid & 7;
    g_mask[(size_t)(rb * 32 + row) * 256 + wb * 8 + w] = sm[row][w];
}

// ---------------------------------------------------------------------------
// Kernel 1: Wh = h@W -> g_Bpack (bf16 m16n8k16 B-frag order, N=64);
// s1, s2 pre-scaled by LOG2E.
// ---------------------------------------------------------------------------
__global__ __launch_bounds__(256) void wh_kernel(const float* __restrict__ h,
                                                 const float* __restrict__ W,
                                                 const float* __restrict__ a) {
    __shared__ float sW[128 * 64];
    __shared__ float shh[16 * 128];
    __shared__ float sr1[16][2], sr2[16][2];
    const int tid = threadIdx.x;
    const int i0  = blockIdx.x * 16;
#pragma unroll
    for (int q = 0; q < 8; q++)
        ((float4*)sW)[tid + q * 256] = ((const float4*)W)[tid + q * 256];
#pragma unroll
    for (int q = 0; q < 2; q++)
        ((float4*)shh)[tid + q * 256] = ((const float4*)(h + (size_t)i0 * 128))[tid + q * 256];
    __syncthreads();

    const int f  = tid & 63;
    const int rq = tid >> 6;
    float acc[4] = {0.f, 0.f, 0.f, 0.f};
#pragma unroll 4
    for (int k = 0; k < 128; k++) {
        const float w = sW[k * 64 + f];
#pragma unroll
        for (int p = 0; p < 4; p++)
            acc[p] = fmaf(shh[(rq * 4 + p) * 128 + k], w, acc[p]);
    }

    const float a1 = a[f], a2 = a[64 + f];
    __nv_bfloat16* bp = (__nv_bfloat16*)g_Bpack;
#pragma unroll
    for (int p = 0; p < 4; p++) {
        const int i = i0 + rq * 4 + p;
        const int kstep = i >> 4, ko = i & 15;
        const int pair = ko >> 3, tig = (ko & 7) >> 1, b = ko & 1;
        bp[(size_t)kstep * 1024 + ((f * 4 + tig) * 2 + pair) * 2 + b] =
            __float2bfloat16(acc[p]);
    }

    float v1[4], v2[4];
#pragma unroll
    for (int p = 0; p < 4; p++) { v1[p] = acc[p] * a1; v2[p] = acc[p] * a2; }
#pragma unroll
    for (int o = 16; o > 0; o >>= 1)
#pragma unroll
        for (int p = 0; p < 4; p++) {
            v1[p] += __shfl_xor_sync(0xFFFFFFFFu, v1[p], o);
            v2[p] += __shfl_xor_sync(0xFFFFFFFFu, v2[p], o);
        }
    if ((f & 31) == 0) {
        const int wh_ = f >> 5;
#pragma unroll
        for (int p = 0; p < 4; p++) {
            sr1[rq * 4 + p][wh_] = v1[p];
            sr2[rq * 4 + p][wh_] = v2[p];
        }
    }
    __syncthreads();
    if (tid < 16) {
        g_s1[i0 + tid] = (sr1[tid][0] + sr1[tid][1]) * LOG2E;
        g_s2[i0 + tid] = (sr2[tid][0] + sr2[tid][1]) * LOG2E;
    }
}

// ---------------------------------------------------------------------------
// Kernel 2: unified. grid 512 (128 rowblocks x 4 jq), 4 CTAs/SM.
// Producer: E/mask in registers (1 tile ahead), ex2 with pre-scaled logits,
// fp32 denominator accumulated in registers. Consumer: NF=4 (N=64 exact),
// B via coalesced LDG.64 from L2-resident Bpack.
// ---------------------------------------------------------------------------
__global__ __launch_bounds__(256, 4) void attn_mma_kernel(const float* __restrict__ efeat,
                                                          const float* __restrict__ a) {
    extern __shared__ char smem[];
    const uint32_t sbase = smem_u32(smem);
    const int tid  = threadIdx.x;
    const int lane = tid & 31;
    const int wid  = tid >> 5;
    const int cta  = blockIdx.x;
    const int i0   = (cta >> 2) * TILE_M;
    const int jq   = cta & 3;

    // -------- producer mapping --------
    const int ls   = lane >> 4;
    const int cf   = lane & 15;
    const int rowb = wid * 8 + ls;
    const int c    = cf * 4;
    const int wsel = cf >> 3;
    const int bsh  = (lane & 7) * 4;
    const int grow0 = i0 + rowb;
    const float ae = a[2 * FOUT] * LOG2E;

    float s1r[4];
#pragma unroll
    for (int k = 0; k < 4; k++) s1r[k] = g_s1[grow0 + 2 * k];

    const float4* __restrict__ ep =
        (const float4*)(efeat + (size_t)grow0 * N_NODES + jq * 2048) + cf;
    const uint32_t* __restrict__ mbase =
        g_mask + (size_t)grow0 * 256 + jq * 64 + wsel;

    // -------- consumer mapping --------
    const int g = lane >> 2, tig = lane & 3;
    const int mh = wid & 3, nh = wid >> 2;
    const uint32_t aoff = (uint32_t)((mh * 16 + g) * 144 + tig * 4);
    const char* __restrict__ bglob = (const char*)g_Bpack
        + (size_t)jq * 32 * B_TILE_BYTES + ((nh * 32 + g) * 4 + tig) * 8;

    // -------- s2 slice to SMEM --------
    {
        const float4* __restrict__ s2g = (const float4*)(g_s2 + jq * 2048);
        const uint32_t dst = sbase + (uint32_t)tid * 32;
#pragma unroll
        for (int q = 0; q < 2; q++) {
            const float4 v = s2g[tid * 2 + q];
            sts128(dst + q * 16, __float_as_uint(v.x), __float_as_uint(v.y),
                   __float_as_uint(v.z), __float_as_uint(v.w));
        }
    }
    __syncthreads();

    // -------- preload E(0), mask(0) --------
    float4 e[4];
    uint32_t mw[4];
#pragma unroll
    for (int k = 0; k < 4; k++) {
        e[k]  = __ldcs(ep + k * 4096);
        mw[k] = __ldg(mbase + k * 512);
    }

    float C[4][4];
#pragma unroll
    for (int n = 0; n < 4; n++)
#pragma unroll
        for (int q = 0; q < 4; q++) C[n][q] = 0.f;
    float den[4] = {0.f, 0.f, 0.f, 0.f};

    for (int t = 0; t < JTILES; t++) {
        // ---- compute P(t) from registers ----
        const uint32_t pbuf = sbase + OFF_P + (uint32_t)(t & 1) * P_SZ;
        const float4 sv = *(const float4*)(smem + (uint32_t)t * 256 + c * 4);
#pragma unroll
        for (int k = 0; k < 4; k++) {
            const float4 ev = e[k];
            const float s1 = s1r[k];
            float e0 = fmaf(ev.x, ae, s1 + sv.x);
            float e1 = fmaf(ev.y, ae, s1 + sv.y);
            float e2 = fmaf(ev.z, ae, s1 + sv.z);
            float e3 = fmaf(ev.w, ae, s1 + sv.w);
            e0 = fmaxf(e0, LRELU_ALPHA * e0);
            e1 = fmaxf(e1, LRELU_ALPHA * e1);
            e2 = fmaxf(e2, LRELU_ALPHA * e2);
            e3 = fmaxf(e3, LRELU_ALPHA * e3);
            const uint32_t m = mw[k] >> bsh;
            const float p0 = (m & 1u) ? ex2(e0) : 0.f;
            const float p1 = (m & 2u) ? ex2(e1) : 0.f;
            const float p2 = (m & 4u) ? ex2(e2) : 0.f;
            const float p3 = (m & 8u) ? ex2(e3) : 0.f;
            den[k] += (p0 + p1) + (p2 + p3);
            const __nv_bfloat162 lo = __floats2bfloat162_rn(p0, p1);
            const __nv_bfloat162 hi = __floats2bfloat162_rn(p2, p3);
            sts64(pbuf + (uint32_t)((rowb + 2 * k) * 144 + c * 2),
                  *(const uint32_t*)&lo, *(const uint32_t*)&hi);
        }

        // ---- prefetch E(t+1), mask(t+1) ----
        if (t < JTILES - 1) {
            const int off = (t + 1) * 16;
#pragma unroll
            for (int k = 0; k < 4; k++) {
                e[k]  = __ldcs(ep + k * 4096 + off);
                mw[k] = __ldg(mbase + k * 512 + (t + 1) * 2);
            }
        }

        __syncthreads();                        // publish P(t)

        // ---- MMA(t): each warp m16 x n32, NF=4 ----
        const char* __restrict__ bt = bglob + (size_t)t * B_TILE_BYTES;
#pragma unroll
        for (int ks = 0; ks < 4; ks++) {
            const uint32_t pa = pbuf + aoff + (uint32_t)ks * 32;
            const uint32_t A0 = lds32(pa);
            const uint32_t A1 = lds32(pa + 8u * 144);
            const uint32_t A2 = lds32(pa + 16);
            const uint32_t A3 = lds32(pa + 8u * 144 + 16);
            const char* bk = bt + ks * 2048;
#pragma unroll
            for (int nf = 0; nf < 4; nf++) {
                const uint2 bf = *(const uint2*)(bk + nf * 256);
                mma_bf16(C[nf], A0, A1, A2, A3, bf.x, bf.y);
            }
        }
    }

    // ---- denominator: reduce over the 16 cf lanes ----
#pragma unroll
    for (int o = 1; o < 16; o <<= 1)
#pragma unroll
        for (int k = 0; k < 4; k++)
            den[k] += __shfl_xor_sync(0xFFFFFFFFu, den[k], o);

    float* pbase = g_part + (size_t)cta * TILE_M * PART_STRIDE;
    if ((lane & 15) == 0) {
#pragma unroll
        for (int k = 0; k < 4; k++)
            pbase[(rowb + 2 * k) * PART_STRIDE + 64] = den[k];
    }

    // ---- numerator partial store ----
    float* prow1 = pbase + (mh * 16 + g) * PART_STRIDE;
    float* prow2 = prow1 + 8 * PART_STRIDE;
#pragma unroll
    for (int nf = 0; nf < 4; nf++) {
        const int gcol = nh * 32 + nf * 8 + 2 * tig;
        *(float2*)(prow1 + gcol) = make_float2(C[nf][0], C[nf][1]);
        *(float2*)(prow2 + gcol) = make_float2(C[nf][2], C[nf][3]);
    }
}

// ---------------------------------------------------------------------------
// Kernel 3: combine the four j-quarter partials, divide, ELU, store.
// ---------------------------------------------------------------------------
__global__ __launch_bounds__(256) void combine_kernel(float* __restrict__ out) {
    const int idx = blockIdx.x * 256 + threadIdx.x;
    const int i   = idx >> 5;
    const int f2  = idx & 31;
    const float* base = g_part + (size_t)(i >> 6) * 4 * TILE_M * PART_STRIDE
                      + (i & 63) * PART_STRIDE;
    float den = 0.f, nx = 0.f, ny = 0.f;
#pragma unroll
    for (int q = 0; q < 4; q++) {
        const float* p = base + (size_t)q * TILE_M * PART_STRIDE;
        den += p[64];
        const float2 v = *(const float2*)(p + f2 * 2);
        nx += v.x;
        ny += v.y;
    }
    const float inv = 1.f / den;
    float v0 = nx * inv, v1 = ny * inv;
    v0 = (v0 > 0.f) ? v0 : expm1f(v0);
    v1 = (v1 > 0.f) ? v1 : expm1f(v1);
    *(float2*)(out + (size_t)i * FOUT + f2 * 2) = make_float2(v0, v1);
}

// ---------------------------------------------------------------------------
extern "C" void kernel_launch(void* const* d_in, const int* in_sizes, int n_in,
                              void* d_out, int out_size) {
    const float* h     = (const float*)d_in[0];
    const int*   adj   = (const int*)  d_in[1];
    const float* efeat = (const float*)d_in[2];
    const float* W     = (const float*)d_in[3];
    const float* a     = (const float*)d_in[4];
    float* out = (float*)d_out;

    cudaFuncSetAttribute(attn_mma_kernel,
                         cudaFuncAttributeMaxDynamicSharedMemorySize, SMEM_BYTES);

    pack_kernel<<<8192, 256>>>(adj);
    wh_kernel<<<512, 256>>>(h, W, a);
    attn_mma_kernel<<<512, 256, SMEM_BYTES>>>(efeat, a);
    combine_kernel<<<1024, 256>>>(out);
}

// round 17
// speedup vs baseline: 1.4397x; 1.4397x over previous
#include <cuda_runtime.h>
#include <cuda_bf16.h>
#include <math.h>
#include <cstdint>

#define N_NODES 8192
#define FOUT 64
#define TILE_M 64
#define JTILES 32            // per CTA: 32 tiles x 64 cols (j-split = 4)
#define LRELU_ALPHA 0.2f

#define E_SZ 16384           // 64 rows x 256 B (E tile stage)
#define P_SZ 9216            // 64 rows x 144 B
#define OFF_P (2 * E_SZ)     // 32768
#define SMEM_BYTES (OFF_P + 2 * P_SZ)   // 51200 -> 4 CTAs/SM
#define PART_STRIDE 66
#define B_TILE_BYTES 9216    // 4 ksteps x 2304 B (72-col pack incl. ones)

// ---------------- device scratch (no allocation allowed) -------------------
__device__ __align__(256) uint32_t g_Bpack[512 * 576 + 256];
__device__ __align__(256) uint32_t g_mask[N_NODES * 256];
__device__ __align__(256) float g_part[512 * TILE_M * PART_STRIDE];
__device__ float g_s1[N_NODES];
__device__ float g_s2[N_NODES];

// ---------------- helpers ----------------------------------------------------
__device__ __forceinline__ uint32_t smem_u32(const void* p) {
    uint32_t a;
    asm("{ .reg .u64 t; cvta.to.shared.u64 t, %1; cvt.u32.u64 %0, t; }" : "=r"(a) : "l"(p));
    return a;
}
__device__ __forceinline__ uint32_t lds32(uint32_t a) {
    uint32_t v; asm("ld.shared.b32 %0, [%1];" : "=r"(v) : "r"(a)); return v;
}
__device__ __forceinline__ float4 lds128f(uint32_t a) {
    float4 v;
    asm("ld.shared.v4.f32 {%0,%1,%2,%3}, [%4];"
        : "=f"(v.x), "=f"(v.y), "=f"(v.z), "=f"(v.w) : "r"(a));
    return v;
}
__device__ __forceinline__ void sts64(uint32_t a, uint32_t v0, uint32_t v1) {
    asm volatile("st.shared.v2.b32 [%0], {%1,%2};" :: "r"(a), "r"(v0), "r"(v1) : "memory");
}
__device__ __forceinline__ void cp16(uint32_t dst, const void* src) {
    asm volatile("cp.async.cg.shared.global [%0], [%1], 16;" :: "r"(dst), "l"(src) : "memory");
}
#define CP_COMMIT() asm volatile("cp.async.commit_group;" ::: "memory")
#define CP_WAIT1()  asm volatile("cp.async.wait_group 1;" ::: "memory")
__device__ __forceinline__ void mma_bf16(float* c,
                                         uint32_t a0, uint32_t a1, uint32_t a2, uint32_t a3,
                                         uint32_t b0, uint32_t b1) {
    asm("mma.sync.aligned.m16n8k16.row.col.f32.bf16.bf16.f32 "
        "{%0,%1,%2,%3},{%4,%5,%6,%7},{%8,%9},{%0,%1,%2,%3};"
        : "+f"(c[0]), "+f"(c[1]), "+f"(c[2]), "+f"(c[3])
        : "r"(a0), "r"(a1), "r"(a2), "r"(a3), "r"(b0), "r"(b1));
}

// ---------------------------------------------------------------------------
// Kernel 0: pack adj>0 into row-major bitmask g_mask[row][word] via ballot.
// ---------------------------------------------------------------------------
__global__ __launch_bounds__(256) void pack_kernel(const int* __restrict__ adj) {
    __shared__ uint32_t sm[32][9];
    const int tid  = threadIdx.x;
    const int lane = tid & 31;
    const int widx = tid >> 5;
    const int rb = blockIdx.x >> 5;
    const int wb = blockIdx.x & 31;
#pragma unroll
    for (int rr = 0; rr < 4; rr++) {
        const int row = rb * 32 + widx * 4 + rr;
        const int* __restrict__ arow = adj + (size_t)row * N_NODES + wb * 256;
#pragma unroll
        for (int w = 0; w < 8; w++) {
            const int v = __ldcs(arow + w * 32 + lane);
            const uint32_t b = __ballot_sync(0xFFFFFFFFu, v > 0);
            if (lane == w) sm[widx * 4 + rr][w] = b;
        }
    }
    __syncthreads();
    const int row = tid >> 3, w = tid & 7;
    g_mask[(size_t)(rb * 32 + row) * 256 + wb * 8 + w] = sm[row][w];
}

// ---------------------------------------------------------------------------
// Kernel 1: Wh = h@W -> g_Bpack (bf16 m16n8k16 B-frag order, 72 cols
// incl. ones col 64); s1, s2.
// ---------------------------------------------------------------------------
__global__ __launch_bounds__(256) void wh_kernel(const float* __restrict__ h,
                                                 const float* __restrict__ W,
                                                 const float* __restrict__ a) {
    __shared__ float sW[128 * 64];
    __shared__ float shh[16 * 128];
    __shared__ float sr1[16][2], sr2[16][2];
    const int tid = threadIdx.x;
    const int i0  = blockIdx.x * 16;
#pragma unroll
    for (int q = 0; q < 8; q++)
        ((float4*)sW)[tid + q * 256] = ((const float4*)W)[tid + q * 256];
#pragma unroll
    for (int q = 0; q < 2; q++)
        ((float4*)shh)[tid + q * 256] = ((const float4*)(h + (size_t)i0 * 128))[tid + q * 256];
    __syncthreads();

    const int f  = tid & 63;
    const int rq = tid >> 6;
    float acc[4] = {0.f, 0.f, 0.f, 0.f};
#pragma unroll 4
    for (int k = 0; k < 128; k++) {
        const float w = sW[k * 64 + f];
#pragma unroll
        for (int p = 0; p < 4; p++)
            acc[p] = fmaf(shh[(rq * 4 + p) * 128 + k], w, acc[p]);
    }

    const float a1 = a[f], a2 = a[64 + f];
    __nv_bfloat16* bp = (__nv_bfloat16*)g_Bpack;
#pragma unroll
    for (int p = 0; p < 4; p++) {
        const int i = i0 + rq * 4 + p;
        const int kstep = i >> 4, ko = i & 15;
        const int pair = ko >> 3, tig = (ko & 7) >> 1, b = ko & 1;
        const size_t sb = (size_t)kstep * 1152;
        bp[sb + ((f * 4 + tig) * 2 + pair) * 2 + b] = __float2bfloat16(acc[p]);
        if (f < 8)
            bp[sb + (((64 + f) * 4 + tig) * 2 + pair) * 2 + b] =
                __float2bfloat16(f == 0 ? 1.0f : 0.0f);
    }

    float v1[4], v2[4];
#pragma unroll
    for (int p = 0; p < 4; p++) { v1[p] = acc[p] * a1; v2[p] = acc[p] * a2; }
#pragma unroll
    for (int o = 16; o > 0; o >>= 1)
#pragma unroll
        for (int p = 0; p < 4; p++) {
            v1[p] += __shfl_xor_sync(0xFFFFFFFFu, v1[p], o);
            v2[p] += __shfl_xor_sync(0xFFFFFFFFu, v2[p], o);
        }
    if ((f & 31) == 0) {
        const int wh_ = f >> 5;
#pragma unroll
        for (int p = 0; p < 4; p++) {
            sr1[rq * 4 + p][wh_] = v1[p];
            sr2[rq * 4 + p][wh_] = v2[p];
        }
    }
    __syncthreads();
    if (tid < 16) {
        g_s1[i0 + tid] = sr1[tid][0] + sr1[tid][1];
        g_s2[i0 + tid] = sr2[tid][0] + sr2[tid][1];
    }
}

// ---------------------------------------------------------------------------
// Kernel 2: unified. grid 512 (128 rowblocks x 4 jq), 4 CTAs/SM.
// E tile: cp.async double-buffer, self-produced/self-consumed per thread,
// issued 2 tiles ahead (full DRAM-latency cover). Mask: registers, 1 ahead.
// Consumer = R10: scalar-LDS A, coalesced B LDG.64 from L2, NF=5 (ones col).
// ---------------------------------------------------------------------------
__global__ __launch_bounds__(256, 4) void attn_mma_kernel(const float* __restrict__ efeat,
                                                          const float* __restrict__ a) {
    extern __shared__ char smem[];
    const uint32_t sbase = smem_u32(smem);
    const int tid  = threadIdx.x;
    const int lane = tid & 31;
    const int wid  = tid >> 5;
    const int cta  = blockIdx.x;
    const int i0   = (cta >> 2) * TILE_M;
    const int jq   = cta & 3;

    // -------- producer mapping --------
    const int ls   = lane >> 4;
    const int cf   = lane & 15;
    const int rowb = wid * 8 + ls;
    const int c    = cf * 4;
    const int wsel = cf >> 3;
    const int bsh  = (lane & 7) * 4;
    const int grow0 = i0 + rowb;
    const float ae = a[2 * FOUT];

    float s1r[4];
#pragma unroll
    for (int k = 0; k < 4; k++) s1r[k] = g_s1[grow0 + 2 * k];

    const float4* __restrict__ ep =
        (const float4*)(efeat + (size_t)grow0 * N_NODES + jq * 2048) + cf;
    const uint32_t* __restrict__ mbase =
        g_mask + (size_t)grow0 * 256 + jq * 64 + wsel;
    const float4* __restrict__ s2p = (const float4*)(g_s2 + jq * 2048 + c);

    // E slot for this thread (self-owned 4 x 16B pieces, stride 512B per piece)
    const uint32_t eslot = sbase + (uint32_t)(rowb * 256 + cf * 16);

    // -------- consumer mapping --------
    const int g = lane >> 2, tig = lane & 3;
    const int mh = wid & 3, nh = wid >> 2;
    const uint32_t aoff = (uint32_t)((mh * 16 + g) * 144 + tig * 4);
    const char* __restrict__ bglob = (const char*)g_Bpack
        + (size_t)jq * 32 * B_TILE_BYTES + ((nh * 40 + g) * 4 + tig) * 8;

    // -------- prologue: cp.async E(0), E(1); mask(0) --------
#pragma unroll
    for (int pt = 0; pt < 2; pt++) {
        const uint32_t ed = eslot + (uint32_t)pt * E_SZ;
#pragma unroll
        for (int k = 0; k < 4; k++)
            cp16(ed + k * 512, ep + k * 4096 + pt * 16);
        CP_COMMIT();
    }
    uint32_t mw[4];
#pragma unroll
    for (int k = 0; k < 4; k++) mw[k] = __ldg(mbase + k * 512);

    float C[5][4];
#pragma unroll
    for (int n = 0; n < 5; n++)
#pragma unroll
        for (int q = 0; q < 4; q++) C[n][q] = 0.f;

    for (int t = 0; t < JTILES; t++) {
        CP_WAIT1();                              // E(t) landed (E(t+1) flying)

        // ---- compute P(t): E from own SMEM slot ----
        const uint32_t eb   = eslot + (uint32_t)(t & 1) * E_SZ;
        const uint32_t pbuf = sbase + OFF_P + (uint32_t)(t & 1) * P_SZ;
        const float4 sv = __ldg(s2p + t * 16);
#pragma unroll
        for (int k = 0; k < 4; k++) {
            const float4 ev = lds128f(eb + k * 512);
            const float s1 = s1r[k];
            float e0 = fmaf(ev.x, ae, s1 + sv.x);
            float e1 = fmaf(ev.y, ae, s1 + sv.y);
            float e2 = fmaf(ev.z, ae, s1 + sv.z);
            float e3 = fmaf(ev.w, ae, s1 + sv.w);
            e0 = fmaxf(e0, LRELU_ALPHA * e0);
            e1 = fmaxf(e1, LRELU_ALPHA * e1);
            e2 = fmaxf(e2, LRELU_ALPHA * e2);
            e3 = fmaxf(e3, LRELU_ALPHA * e3);
            const uint32_t m = mw[k] >> bsh;
            const float p0 = (m & 1u) ? __expf(e0) : 0.f;
            const float p1 = (m & 2u) ? __expf(e1) : 0.f;
            const float p2 = (m & 4u) ? __expf(e2) : 0.f;
            const float p3 = (m & 8u) ? __expf(e3) : 0.f;
            const __nv_bfloat162 lo = __floats2bfloat162_rn(p0, p1);
            const __nv_bfloat162 hi = __floats2bfloat162_rn(p2, p3);
            sts64(pbuf + (uint32_t)((rowb + 2 * k) * 144 + c * 2),
                  *(const uint32_t*)&lo, *(const uint32_t*)&hi);
        }

        // ---- issue E(t+2) into the slot just read (self-owned, WAR-safe) ----
        if (t < JTILES - 2) {
#pragma unroll
            for (int k = 0; k < 4; k++)
                cp16(eb + k * 512, ep + k * 4096 + (t + 2) * 16);
        }
        CP_COMMIT();                             // one group per tile (may be empty)

        // ---- mask(t+1) prefetch ----
        if (t < JTILES - 1) {
#pragma unroll
            for (int k = 0; k < 4; k++)
                mw[k] = __ldg(mbase + k * 512 + (t + 1) * 2);
        }

        __syncthreads();                         // publish P(t)

        // ---- MMA(t): each warp m16 x n40 ----
        const char* __restrict__ bt = bglob + (size_t)t * B_TILE_BYTES;
#pragma unroll
        for (int ks = 0; ks < 4; ks++) {
            const uint32_t pa = pbuf + aoff + (uint32_t)ks * 32;
            const uint32_t A0 = lds32(pa);
            const uint32_t A1 = lds32(pa + 8u * 144);
            const uint32_t A2 = lds32(pa + 16);
            const uint32_t A3 = lds32(pa + 8u * 144 + 16);
            const char* bk = bt + ks * 2304;
#pragma unroll
            for (int nf = 0; nf < 5; nf++) {
                const uint2 bf = *(const uint2*)(bk + nf * 256);
                mma_bf16(C[nf], A0, A1, A2, A3, bf.x, bf.y);
            }
        }
    }

    // ---- partial store (ones col 64 = denominator) ----
    float* pbase = g_part + (size_t)cta * TILE_M * PART_STRIDE;
    float* prow1 = pbase + (mh * 16 + g) * PART_STRIDE;
    float* prow2 = prow1 + 8 * PART_STRIDE;
#pragma unroll
    for (int nf = 0; nf < 5; nf++) {
        const int gcol = nh * 40 + nf * 8 + 2 * tig;
        if (gcol < 64) {
            *(float2*)(prow1 + gcol) = make_float2(C[nf][0], C[nf][1]);
            *(float2*)(prow2 + gcol) = make_float2(C[nf][2], C[nf][3]);
        } else if (gcol == 64) {
            prow1[64] = C[nf][0];
            prow2[64] = C[nf][2];
        }
    }
}

// ---------------------------------------------------------------------------
// Kernel 3: combine the four j-quarter partials, divide, ELU, store.
// ---------------------------------------------------------------------------
__global__ __launch_bounds__(256) void combine_kernel(float* __restrict__ out) {
    const int idx = blockIdx.x * 256 + threadIdx.x;
    const int i   = idx >> 5;
    const int f2  = idx & 31;
    const float* base = g_part + (size_t)(i >> 6) * 4 * TILE_M * PART_STRIDE
                      + (i & 63) * PART_STRIDE;
    float den = 0.f, nx = 0.f, ny = 0.f;
#pragma unroll
    for (int q = 0; q < 4; q++) {
        const float* p = base + (size_t)q * TILE_M * PART_STRIDE;
        den += p[64];
        const float2 v = *(const float2*)(p + f2 * 2);
        nx += v.x;
        ny += v.y;
    }
    const float inv = 1.f / den;
    float v0 = nx * inv, v1 = ny * inv;
    v0 = (v0 > 0.f) ? v0 : expm1f(v0);
    v1 = (v1 > 0.f) ? v1 : expm1f(v1);
    *(float2*)(out + (size_t)i * FOUT + f2 * 2) = make_float2(v0, v1);
}

// ---------------------------------------------------------------------------
extern "C" void kernel_launch(void* const* d_in, const int* in_sizes, int n_in,
                              void* d_out, int out_size) {
    const float* h     = (const float*)d_in[0];
    const int*   adj   = (const int*)  d_in[1];
    const float* efeat = (const float*)d_in[2];
    const float* W     = (const float*)d_in[3];
    const float* a     = (const float*)d_in[4];
    float* out = (float*)d_out;

    cudaFuncSetAttribute(attn_mma_kernel,
                         cudaFuncAttributeMaxDynamicSharedMemorySize, SMEM_BYTES);

    pack_kernel<<<8192, 256>>>(adj);
    wh_kernel<<<512, 256>>>(h, W, a);
    attn_mma_kernel<<<512, 256, SMEM_BYTES>>>(efeat, a);
    combine_kernel<<<1024, 256>>>(out);
}